// round 3
// baseline (speedup 1.0000x reference)
#include <cuda_runtime.h>
#include <cstdint>

// PCEN: EMA over time + pointwise compression.
// x: [B=32, T=8192, F=128] f32.  out same shape.
//
// Strategy: chunked EMA with 512-step warm-up (decay 0.975^512 ~ 2.4e-6 kills
// seed error, far below the 1e-3 gate). One warp per (b, chunk); 32 lanes x
// float4 cover F=128 -> one coalesced 512B row per time step.
// Depth-16 register ring of float4 loads keeps ~8KB/warp in flight.

#define T_DIM   8192
#define F_DIM   128
#define B_DIM   32
#define L_CHUNK 1024
#define N_CHUNK (T_DIM / L_CHUNK)   // 8
#define WARM    512
#define RDEPTH  16                  // ring depth (float4 rows in flight)

#define EPS_C    1e-6f
#define S_C      0.025f
#define OMS_C    0.975f
#define ALPHA_C  0.98f
#define SQRT_DELTA_C 1.41421356237309515f  // sqrt(2.0)

__device__ __forceinline__ float sqrt_approx(float x) {
    float y;
    asm("sqrt.approx.f32 %0, %1;" : "=f"(y) : "f"(x));
    return y;
}

__device__ __forceinline__ float lg2_approx(float x) {
    float y;
    asm("lg2.approx.f32 %0, %1;" : "=f"(y) : "f"(x));
    return y;
}

__device__ __forceinline__ float ex2_approx(float x) {
    float y;
    asm("ex2.approx.f32 %0, %1;" : "=f"(y) : "f"(x));
    return y;
}

// (m + eps)^(-alpha) via MUFU lg2/ex2
__device__ __forceinline__ float inv_pow_alpha(float m) {
    return ex2_approx(-ALPHA_C * lg2_approx(m + EPS_C));
}

__device__ __forceinline__ void ema_update(float4& m, const float4& xv) {
    m.x = fmaf(OMS_C, m.x, S_C * xv.x);
    m.y = fmaf(OMS_C, m.y, S_C * xv.y);
    m.z = fmaf(OMS_C, m.z, S_C * xv.z);
    m.w = fmaf(OMS_C, m.w, S_C * xv.w);
}

__device__ __forceinline__ float4 pcen_out(const float4& xv, const float4& m) {
    float4 o;
    o.x = sqrt_approx(fmaf(xv.x, inv_pow_alpha(m.x), 2.0f)) - SQRT_DELTA_C;
    o.y = sqrt_approx(fmaf(xv.y, inv_pow_alpha(m.y), 2.0f)) - SQRT_DELTA_C;
    o.z = sqrt_approx(fmaf(xv.z, inv_pow_alpha(m.z), 2.0f)) - SQRT_DELTA_C;
    o.w = sqrt_approx(fmaf(xv.w, inv_pow_alpha(m.w), 2.0f)) - SQRT_DELTA_C;
    return o;
}

__global__ void __launch_bounds__(32, 32)
pcen_kernel(const float4* __restrict__ x, float4* __restrict__ out) {
    const int wid  = blockIdx.x;          // 0 .. B*N_CHUNK-1  (one warp per block)
    const int lane = threadIdx.x;         // lane covers f = 4*lane .. 4*lane+3

    const int b = wid >> 3;               // / N_CHUNK
    const int c = wid & (N_CHUNK - 1);

    const int warm = (c == 0) ? 0 : WARM;
    const int t_s  = c * L_CHUNK - warm;  // first time step this warp touches
    const int N    = L_CHUNK + warm;      // total steps (multiple of RDEPTH)

    const int ROWF4 = F_DIM / 4;          // 32 float4 per time row

    const float4* px = x   + ((size_t)(b * T_DIM + t_s)) * ROWF4 + lane;
    float4*       po = out + ((size_t)(b * T_DIM + t_s)) * ROWF4 + lane;

    // ---- prologue: fill ring ----
    float4 buf[RDEPTH];
#pragma unroll
    for (int i = 0; i < RDEPTH; i++)
        buf[i] = px[(size_t)i * ROWF4];

    // Seed: m = x[t_s]. Since ema_update(m, x) with m == x is a fixed point,
    // the first loop iteration needs no special case. For chunk 0 this is the
    // exact M[0] = x[0]; for warm chunks it's the warm-up seed.
    float4 m = buf[0];

    int r = 0;

    // ---- warm-up tiles: EMA only, no output ----
    for (; r < warm; r += RDEPTH) {
#pragma unroll
        for (int i = 0; i < RDEPTH; i++) {
            float4 xv = buf[i];
            int nidx = min(r + RDEPTH + i, N - 1);   // clamp (redundant re-read, safe)
            buf[i] = px[(size_t)nidx * ROWF4];       // refill slot: depth-16 pipeline
            ema_update(m, xv);
        }
    }

    // ---- emit tiles: EMA + PCEN output ----
    for (; r < N; r += RDEPTH) {
#pragma unroll
        for (int i = 0; i < RDEPTH; i++) {
            float4 xv = buf[i];
            int nidx = min(r + RDEPTH + i, N - 1);
            buf[i] = px[(size_t)nidx * ROWF4];
            ema_update(m, xv);
            po[(size_t)(r + i) * ROWF4] = pcen_out(xv, m);
        }
    }
}

extern "C" void kernel_launch(void* const* d_in, const int* in_sizes, int n_in,
                              void* d_out, int out_size) {
    (void)in_sizes; (void)n_in; (void)out_size;
    const float4* x = (const float4*)d_in[0];
    float4* o = (float4*)d_out;
    pcen_kernel<<<B_DIM * N_CHUNK, 32>>>(x, o);
}

// round 6
// speedup vs baseline: 3.1624x; 3.1624x over previous
#include <cuda_runtime.h>
#include <cstdint>

// PCEN: EMA over time + pointwise compression.
// x: [B=32, T=8192, F=128] f32.  out same shape.
//
// Chunked EMA, 384-step warm-up (0.975^384 ~ 6e-5 kills seed error).
// One warp per (b, chunk): 32 lanes x float4 = one coalesced 512B row/step.
// Depth-16 register ring of float4 loads -> 8KB in flight per warp.
// 4 warps/block so warps spread over all 4 SMSPs; regs uncapped (128,2).

#define T_DIM   8192
#define F_DIM   128
#define B_DIM   32
#define L_CHUNK 512
#define N_CHUNK (T_DIM / L_CHUNK)   // 16
#define WARM    384
#define RDEPTH  16                  // ring depth (float4 rows in flight)
#define WARPS_PER_BLOCK 4

#define EPS_C    1e-6f
#define S_C      0.025f
#define OMS_C    0.975f
#define ALPHA_C  0.98f
#define SQRT_DELTA_C 1.41421356237309515f  // sqrt(2.0)

__device__ __forceinline__ float sqrt_approx(float x) {
    float y;
    asm("sqrt.approx.f32 %0, %1;" : "=f"(y) : "f"(x));
    return y;
}
__device__ __forceinline__ float lg2_approx(float x) {
    float y;
    asm("lg2.approx.f32 %0, %1;" : "=f"(y) : "f"(x));
    return y;
}
__device__ __forceinline__ float ex2_approx(float x) {
    float y;
    asm("ex2.approx.f32 %0, %1;" : "=f"(y) : "f"(x));
    return y;
}

// (m + eps)^(-alpha) via MUFU lg2/ex2
__device__ __forceinline__ float inv_pow_alpha(float m) {
    return ex2_approx(-ALPHA_C * lg2_approx(m + EPS_C));
}

__device__ __forceinline__ void ema_update(float4& m, const float4& xv) {
    m.x = fmaf(OMS_C, m.x, S_C * xv.x);
    m.y = fmaf(OMS_C, m.y, S_C * xv.y);
    m.z = fmaf(OMS_C, m.z, S_C * xv.z);
    m.w = fmaf(OMS_C, m.w, S_C * xv.w);
}

__device__ __forceinline__ float4 pcen_out(const float4& xv, const float4& m) {
    float4 o;
    o.x = sqrt_approx(fmaf(xv.x, inv_pow_alpha(m.x), 2.0f)) - SQRT_DELTA_C;
    o.y = sqrt_approx(fmaf(xv.y, inv_pow_alpha(m.y), 2.0f)) - SQRT_DELTA_C;
    o.z = sqrt_approx(fmaf(xv.z, inv_pow_alpha(m.z), 2.0f)) - SQRT_DELTA_C;
    o.w = sqrt_approx(fmaf(xv.w, inv_pow_alpha(m.w), 2.0f)) - SQRT_DELTA_C;
    return o;
}

__device__ __forceinline__ void store_cs(float4* p, const float4& v) {
    asm volatile("st.global.cs.v4.f32 [%0], {%1,%2,%3,%4};"
                 :: "l"(p), "f"(v.x), "f"(v.y), "f"(v.z), "f"(v.w) : "memory");
}

__global__ void __launch_bounds__(32 * WARPS_PER_BLOCK, 2)
pcen_kernel(const float4* __restrict__ x, float4* __restrict__ out) {
    const int lane = threadIdx.x & 31;            // covers f = 4*lane .. 4*lane+3
    const int wid  = blockIdx.x * WARPS_PER_BLOCK + (threadIdx.x >> 5);

    const int b = wid / N_CHUNK;
    const int c = wid % N_CHUNK;

    const int warm = (c == 0) ? 0 : WARM;
    const int t_s  = c * L_CHUNK - warm;          // first time step this warp touches
    const int N    = L_CHUNK + warm;              // total steps (multiple of RDEPTH)

    const int ROWF4 = F_DIM / 4;                  // 32 float4 per time row

    const float4* px = x   + ((size_t)(b * T_DIM + t_s)) * ROWF4 + lane;
    float4*       po = out + ((size_t)(b * T_DIM + t_s)) * ROWF4 + lane;

    // ---- prologue: fill ring ----
    float4 buf[RDEPTH];
#pragma unroll
    for (int i = 0; i < RDEPTH; i++)
        buf[i] = px[(size_t)i * ROWF4];

    // Seed m = x[t_s]; ema_update(m, x) with m == x is a fixed point, so the
    // first iteration needs no special case. Chunk 0: exact M[0] = x[0].
    float4 m = buf[0];

    int r = 0;

    // ---- warm-up tiles: EMA only, no output ----
    for (; r < warm; r += RDEPTH) {
#pragma unroll
        for (int i = 0; i < RDEPTH; i++) {
            float4 xv = buf[i];
            int nidx = min(r + RDEPTH + i, N - 1);   // clamp (redundant re-read, safe)
            buf[i] = px[(size_t)nidx * ROWF4];       // refill slot: depth-16 pipeline
            ema_update(m, xv);
        }
    }

    // ---- emit tiles: EMA + PCEN output ----
    for (; r < N; r += RDEPTH) {
#pragma unroll
        for (int i = 0; i < RDEPTH; i++) {
            float4 xv = buf[i];
            int nidx = min(r + RDEPTH + i, N - 1);
            buf[i] = px[(size_t)nidx * ROWF4];
            ema_update(m, xv);
            store_cs(po + (size_t)(r + i) * ROWF4, pcen_out(xv, m));
        }
    }
}

extern "C" void kernel_launch(void* const* d_in, const int* in_sizes, int n_in,
                              void* d_out, int out_size) {
    (void)in_sizes; (void)n_in; (void)out_size;
    const float4* x = (const float4*)d_in[0];
    float4* o = (float4*)d_out;
    const int total_warps = B_DIM * N_CHUNK;                 // 512
    pcen_kernel<<<total_warps / WARPS_PER_BLOCK, 32 * WARPS_PER_BLOCK>>>(x, o);
}

// round 7
// speedup vs baseline: 3.8631x; 1.2216x over previous
#include <cuda_runtime.h>
#include <cstdint>

// PCEN: EMA over time + pointwise compression.
// x: [B=32, T=8192, F=128] f32.  out same shape.
//
// Chunked EMA, 256-step warm-up (0.975^256 ~ 1.5e-3 seed decay; measured
// output attenuation ~0.1x -> ~1.4e-4 rel err, safely under 1e-3).
// One warp per (b, chunk): 32 lanes x float4 = one coalesced 512B row/step.
// Depth-16 register ring -> 8KB/warp in flight. 1024 warps in 256 blocks of
// 4 warps -> ~2 warps/SMSP on all 148 SMs (overlaps MUFU + load latency).

#define T_DIM   8192
#define F_DIM   128
#define B_DIM   32
#define L_CHUNK 256
#define N_CHUNK (T_DIM / L_CHUNK)   // 32
#define WARM    256
#define RDEPTH  16                  // ring depth (float4 rows in flight)
#define WARPS_PER_BLOCK 4

#define EPS_C    1e-6f
#define S_C      0.025f
#define OMS_C    0.975f
#define ALPHA_C  0.98f
#define SQRT_DELTA_C 1.41421356237309515f  // sqrt(2.0)

__device__ __forceinline__ float sqrt_approx(float x) {
    float y;
    asm("sqrt.approx.f32 %0, %1;" : "=f"(y) : "f"(x));
    return y;
}
__device__ __forceinline__ float lg2_approx(float x) {
    float y;
    asm("lg2.approx.f32 %0, %1;" : "=f"(y) : "f"(x));
    return y;
}
__device__ __forceinline__ float ex2_approx(float x) {
    float y;
    asm("ex2.approx.f32 %0, %1;" : "=f"(y) : "f"(x));
    return y;
}

// (m + eps)^(-alpha) via MUFU lg2/ex2
__device__ __forceinline__ float inv_pow_alpha(float m) {
    return ex2_approx(-ALPHA_C * lg2_approx(m + EPS_C));
}

__device__ __forceinline__ void ema_update(float4& m, const float4& xv) {
    m.x = fmaf(OMS_C, m.x, S_C * xv.x);
    m.y = fmaf(OMS_C, m.y, S_C * xv.y);
    m.z = fmaf(OMS_C, m.z, S_C * xv.z);
    m.w = fmaf(OMS_C, m.w, S_C * xv.w);
}

__device__ __forceinline__ float4 pcen_out(const float4& xv, const float4& m) {
    float4 o;
    o.x = sqrt_approx(fmaf(xv.x, inv_pow_alpha(m.x), 2.0f)) - SQRT_DELTA_C;
    o.y = sqrt_approx(fmaf(xv.y, inv_pow_alpha(m.y), 2.0f)) - SQRT_DELTA_C;
    o.z = sqrt_approx(fmaf(xv.z, inv_pow_alpha(m.z), 2.0f)) - SQRT_DELTA_C;
    o.w = sqrt_approx(fmaf(xv.w, inv_pow_alpha(m.w), 2.0f)) - SQRT_DELTA_C;
    return o;
}

__device__ __forceinline__ void store_cs(float4* p, const float4& v) {
    asm volatile("st.global.cs.v4.f32 [%0], {%1,%2,%3,%4};"
                 :: "l"(p), "f"(v.x), "f"(v.y), "f"(v.z), "f"(v.w) : "memory");
}

__global__ void __launch_bounds__(32 * WARPS_PER_BLOCK, 2)
pcen_kernel(const float4* __restrict__ x, float4* __restrict__ out) {
    const int lane = threadIdx.x & 31;            // covers f = 4*lane .. 4*lane+3
    const int wid  = blockIdx.x * WARPS_PER_BLOCK + (threadIdx.x >> 5);

    const int b = wid / N_CHUNK;
    const int c = wid % N_CHUNK;

    const int warm = (c == 0) ? 0 : WARM;
    const int t_s  = c * L_CHUNK - warm;          // first time step this warp touches
    const int N    = L_CHUNK + warm;              // total steps (multiple of RDEPTH)

    const int ROWF4 = F_DIM / 4;                  // 32 float4 per time row

    const float4* px = x   + ((size_t)(b * T_DIM + t_s)) * ROWF4 + lane;
    float4*       po = out + ((size_t)(b * T_DIM + t_s)) * ROWF4 + lane;

    // ---- prologue: fill ring ----
    float4 buf[RDEPTH];
#pragma unroll
    for (int i = 0; i < RDEPTH; i++)
        buf[i] = px[(size_t)i * ROWF4];

    // Seed m = x[t_s]; ema_update(m, x) with m == x is a fixed point, so the
    // first iteration needs no special case. Chunk 0: exact M[0] = x[0].
    float4 m = buf[0];

    int r = 0;

    // ---- warm-up tiles: EMA only, no output ----
    for (; r < warm; r += RDEPTH) {
#pragma unroll
        for (int i = 0; i < RDEPTH; i++) {
            float4 xv = buf[i];
            int nidx = min(r + RDEPTH + i, N - 1);   // clamp (redundant re-read, safe)
            buf[i] = px[(size_t)nidx * ROWF4];       // refill slot: depth-16 pipeline
            ema_update(m, xv);
        }
    }

    // ---- emit tiles: EMA + PCEN output ----
    for (; r < N; r += RDEPTH) {
#pragma unroll
        for (int i = 0; i < RDEPTH; i++) {
            float4 xv = buf[i];
            int nidx = min(r + RDEPTH + i, N - 1);
            buf[i] = px[(size_t)nidx * ROWF4];
            ema_update(m, xv);
            store_cs(po + (size_t)(r + i) * ROWF4, pcen_out(xv, m));
        }
    }
}

extern "C" void kernel_launch(void* const* d_in, const int* in_sizes, int n_in,
                              void* d_out, int out_size) {
    (void)in_sizes; (void)n_in; (void)out_size;
    const float4* x = (const float4*)d_in[0];
    float4* o = (float4*)d_out;
    const int total_warps = B_DIM * N_CHUNK;                 // 1024
    pcen_kernel<<<total_warps / WARPS_PER_BLOCK, 32 * WARPS_PER_BLOCK>>>(x, o);
}

// round 9
// speedup vs baseline: 4.1581x; 1.0764x over previous
#include <cuda_runtime.h>
#include <cstdint>

// PCEN: EMA over time + pointwise compression.
// x: [B=32, T=8192, F=128] f32.  out same shape.
//
// Chunked EMA, 256-step warm-up (seed decay 0.975^256 ~ 1.5e-3 -> measured
// rel_err ~2e-4, safely under the 1e-3 gate; do NOT shrink warm further).
// F split across 2 warps per (b, chunk): 32 lanes x float2 = 256B row/step,
// fully coalesced. 2048 warps total (same bytes as the float4 version,
// double the latency-hiding). Depth-16 float2 ring -> 4KB/warp in flight.

#define T_DIM   8192
#define F_DIM   128
#define B_DIM   32
#define L_CHUNK 256
#define N_CHUNK (T_DIM / L_CHUNK)   // 32
#define WARM    256
#define RDEPTH  16                  // ring depth (float2 rows in flight)
#define WARPS_PER_BLOCK 8           // 256 threads/block

#define EPS_C    1e-6f
#define S_C      0.025f
#define OMS_C    0.975f
#define ALPHA_C  0.98f
#define SQRT_DELTA_C 1.41421356237309515f  // sqrt(2.0)

__device__ __forceinline__ float sqrt_approx(float x) {
    float y;
    asm("sqrt.approx.f32 %0, %1;" : "=f"(y) : "f"(x));
    return y;
}
__device__ __forceinline__ float lg2_approx(float x) {
    float y;
    asm("lg2.approx.f32 %0, %1;" : "=f"(y) : "f"(x));
    return y;
}
__device__ __forceinline__ float ex2_approx(float x) {
    float y;
    asm("ex2.approx.f32 %0, %1;" : "=f"(y) : "f"(x));
    return y;
}

// (m + eps)^(-alpha) via MUFU lg2/ex2
__device__ __forceinline__ float inv_pow_alpha(float m) {
    return ex2_approx(-ALPHA_C * lg2_approx(m + EPS_C));
}

__device__ __forceinline__ void ema_update(float2& m, const float2& xv) {
    m.x = fmaf(OMS_C, m.x, S_C * xv.x);
    m.y = fmaf(OMS_C, m.y, S_C * xv.y);
}

__device__ __forceinline__ float2 pcen_out(const float2& xv, const float2& m) {
    float2 o;
    o.x = sqrt_approx(fmaf(xv.x, inv_pow_alpha(m.x), 2.0f)) - SQRT_DELTA_C;
    o.y = sqrt_approx(fmaf(xv.y, inv_pow_alpha(m.y), 2.0f)) - SQRT_DELTA_C;
    return o;
}

__device__ __forceinline__ void store_cs(float2* p, const float2& v) {
    asm volatile("st.global.cs.v2.f32 [%0], {%1,%2};"
                 :: "l"(p), "f"(v.x), "f"(v.y) : "memory");
}

__global__ void __launch_bounds__(32 * WARPS_PER_BLOCK, 2)
pcen_kernel(const float2* __restrict__ x, float2* __restrict__ out) {
    const int lane = threadIdx.x & 31;
    const int wid  = blockIdx.x * WARPS_PER_BLOCK + (threadIdx.x >> 5);

    const int half = wid & 1;                     // which F half (0: f<64, 1: f>=64)
    const int cw   = wid >> 1;                    // chunk-warp id
    const int b    = cw / N_CHUNK;
    const int c    = cw % N_CHUNK;

    const int warm = (c == 0) ? 0 : WARM;
    const int t_s  = c * L_CHUNK - warm;          // first time step this warp touches
    const int N    = L_CHUNK + warm;              // total steps (multiple of RDEPTH)

    const int ROWF2 = F_DIM / 2;                  // 64 float2 per time row

    const size_t base = (size_t)(b * T_DIM + t_s) * ROWF2 + half * 32 + lane;
    const float2* px = x   + base;
    float2*       po = out + base;

    // ---- prologue: fill ring ----
    float2 buf[RDEPTH];
#pragma unroll
    for (int i = 0; i < RDEPTH; i++)
        buf[i] = px[(size_t)i * ROWF2];

    // Seed m = x[t_s]; ema_update(m, x) with m == x is a fixed point, so the
    // first iteration needs no special case. Chunk 0: exact M[0] = x[0].
    float2 m = buf[0];

    int r = 0;

    // ---- warm-up tiles: EMA only, no output ----
    for (; r < warm; r += RDEPTH) {
#pragma unroll
        for (int i = 0; i < RDEPTH; i++) {
            float2 xv = buf[i];
            int nidx = min(r + RDEPTH + i, N - 1);   // clamp (redundant re-read, safe)
            buf[i] = px[(size_t)nidx * ROWF2];       // refill slot: depth-16 pipeline
            ema_update(m, xv);
        }
    }

    // ---- emit tiles: EMA + PCEN output ----
    for (; r < N; r += RDEPTH) {
#pragma unroll
        for (int i = 0; i < RDEPTH; i++) {
            float2 xv = buf[i];
            int nidx = min(r + RDEPTH + i, N - 1);
            buf[i] = px[(size_t)nidx * ROWF2];
            ema_update(m, xv);
            store_cs(po + (size_t)(r + i) * ROWF2, pcen_out(xv, m));
        }
    }
}

extern "C" void kernel_launch(void* const* d_in, const int* in_sizes, int n_in,
                              void* d_out, int out_size) {
    (void)in_sizes; (void)n_in; (void)out_size;
    const float2* x = (const float2*)d_in[0];
    float2* o = (float2*)d_out;
    const int total_warps = B_DIM * N_CHUNK * 2;             // 2048
    pcen_kernel<<<total_warps / WARPS_PER_BLOCK, 32 * WARPS_PER_BLOCK>>>(x, o);
}